// round 10
// baseline (speedup 1.0000x reference)
#include <cuda_runtime.h>
#include <cuda_bf16.h>
#include <stdint.h>
#include <math.h>

#define B_ 4
#define N_ 4096
#define C_ 256
#define D_ 64

// ---- scratch (allocation-free contract) -----------------------------------
__device__ uint16_t g_ghi[B_ * N_ * D_];   // bf16 hi of g
__device__ uint16_t g_glo[B_ * N_ * D_];   // bf16 lo of g
__device__ uint16_t g_fhi[B_ * N_ * D_];   // bf16 hi of f
__device__ uint16_t g_flo[B_ * N_ * D_];   // bf16 lo of f
__device__ float    g_h[B_ * N_ * C_];     // only touched if gamma != 0
__device__ float    g_rowsum[B_ * N_];     // sums, then reciprocals (in place)

__device__ __forceinline__ uint32_t smem_u32(const void* p) {
    uint32_t a;
    asm("{ .reg .u64 t; cvta.to.shared.u64 t, %1; cvt.u32.u64 %0, t; }" : "=r"(a) : "l"(p));
    return a;
}

// ---------------------------------------------------------------------------
__global__ void zero_rowsum_kernel() {
    int i = blockIdx.x * blockDim.x + threadIdx.x;
    if (i < B_ * N_) g_rowsum[i] = 0.0f;
}

__global__ void inv_rowsum_kernel() {
    int i = blockIdx.x * blockDim.x + threadIdx.x;
    if (i < B_ * N_) g_rowsum[i] = 1.0f / g_rowsum[i];
}

// ---------------------------------------------------------------------------
// f = x@Wf, g = x@Wg, emitted as bf16 hi/lo split.
// ---------------------------------------------------------------------------
__global__ void __launch_bounds__(256) fg_kernel(const float* __restrict__ x,
                                                 const float* __restrict__ Wf,
                                                 const float* __restrict__ Wg) {
    __shared__ float xs[C_][32];
    __shared__ float ws[2][16][D_];

    const int b    = blockIdx.y;
    const int row0 = blockIdx.x * 32;
    const int r    = threadIdx.x >> 3;
    const int dg   = threadIdx.x & 7;

    {
        const float4* src = reinterpret_cast<const float4*>(
            x + ((size_t)b * N_ + row0 + r) * C_ + dg * 32);
#pragma unroll
        for (int i = 0; i < 8; i++) {
            float4 v = src[i];
            int c = dg * 32 + i * 4;
            xs[c + 0][r] = v.x; xs[c + 1][r] = v.y;
            xs[c + 2][r] = v.z; xs[c + 3][r] = v.w;
        }
    }

    float accf[8] = {}, accg[8] = {};
    for (int c0 = 0; c0 < C_; c0 += 16) {
        __syncthreads();
        {
            const float4* wf4 = reinterpret_cast<const float4*>(Wf + c0 * D_);
            const float4* wg4 = reinterpret_cast<const float4*>(Wg + c0 * D_);
            reinterpret_cast<float4*>(&ws[0][0][0])[threadIdx.x] = wf4[threadIdx.x];
            reinterpret_cast<float4*>(&ws[1][0][0])[threadIdx.x] = wg4[threadIdx.x];
        }
        __syncthreads();
#pragma unroll
        for (int cc = 0; cc < 16; cc++) {
            float xv = xs[c0 + cc][r];
#pragma unroll
            for (int j = 0; j < 8; j++) {
                accf[j] = fmaf(xv, ws[0][cc][dg * 8 + j], accf[j]);
                accg[j] = fmaf(xv, ws[1][cc][dg * 8 + j], accg[j]);
            }
        }
    }

    uint4 fh, fl, gh, gl;
    uint16_t* fhp = (uint16_t*)&fh; uint16_t* flp = (uint16_t*)&fl;
    uint16_t* ghp = (uint16_t*)&gh; uint16_t* glp = (uint16_t*)&gl;
#pragma unroll
    for (int j = 0; j < 8; j++) {
        __nv_bfloat16 h1 = __float2bfloat16_rn(accf[j]);
        __nv_bfloat16 l1 = __float2bfloat16_rn(accf[j] - __bfloat162float(h1));
        __nv_bfloat16 h2 = __float2bfloat16_rn(accg[j]);
        __nv_bfloat16 l2 = __float2bfloat16_rn(accg[j] - __bfloat162float(h2));
        fhp[j] = *(uint16_t*)&h1; flp[j] = *(uint16_t*)&l1;
        ghp[j] = *(uint16_t*)&h2; glp[j] = *(uint16_t*)&l2;
    }
    size_t off = ((size_t)b * N_ + row0 + r) * D_ + dg * 8;
    *reinterpret_cast<uint4*>(g_fhi + off) = fh;
    *reinterpret_cast<uint4*>(g_flo + off) = fl;
    *reinterpret_cast<uint4*>(g_ghi + off) = gh;
    *reinterpret_cast<uint4*>(g_glo + off) = gl;
}

// ---------------------------------------------------------------------------
// Shared GEMM core: 128x128 tile, K=64, bf16-split 3-term, 8 warps 4x2,
// warp tile 32x64.
// ---------------------------------------------------------------------------
#define PADE 72   // bf16 elements per smem row (64 + 8 pad => 144B stride)
#define TILE_BYTES (128 * PADE * 2)

__device__ __forceinline__ void load_tiles(char* sAhi, char* sAlo, char* sBhi, char* sBlo,
                                           int b, int row0, int col0, int tid) {
    for (int i = tid; i < 1024; i += 256) {
        int r = i >> 3, c = i & 7;
        int so = r * (PADE * 2) + c * 16;
        size_t ga = ((size_t)b * N_ + row0 + r) * D_ + c * 8;
        size_t gb = ((size_t)b * N_ + col0 + r) * D_ + c * 8;
        *reinterpret_cast<uint4*>(sAhi + so) = *reinterpret_cast<const uint4*>(g_ghi + ga);
        *reinterpret_cast<uint4*>(sAlo + so) = *reinterpret_cast<const uint4*>(g_glo + ga);
        *reinterpret_cast<uint4*>(sBhi + so) = *reinterpret_cast<const uint4*>(g_fhi + gb);
        *reinterpret_cast<uint4*>(sBlo + so) = *reinterpret_cast<const uint4*>(g_flo + gb);
    }
}

__device__ __forceinline__ void gemm_tile(char* sAhi, char* sAlo, char* sBhi, char* sBlo,
                                          uint32_t aRow, uint32_t aK8,
                                          uint32_t bRow, uint32_t bK8,
                                          float d[2][8][4]) {
#pragma unroll
    for (int term = 0; term < 3; term++) {
        const uint32_t Abase = smem_u32(term == 2 ? sAlo : sAhi);
        const uint32_t Bbase = smem_u32(term == 1 ? sBlo : sBhi);
#pragma unroll
        for (int k0 = 0; k0 < 64; k0 += 16) {
            uint32_t a[2][4];
#pragma unroll
            for (int mi = 0; mi < 2; mi++) {
                uint32_t addr = Abase + (aRow + mi * 16) * (PADE * 2) + (k0 + aK8) * 2;
                asm volatile("ldmatrix.sync.aligned.m8n8.x4.shared.b16 {%0,%1,%2,%3}, [%4];"
                             : "=r"(a[mi][0]), "=r"(a[mi][1]), "=r"(a[mi][2]), "=r"(a[mi][3])
                             : "r"(addr));
            }
#pragma unroll
            for (int ni = 0; ni < 8; ni++) {
                uint32_t bb[2];
                uint32_t addr = Bbase + (bRow + ni * 8) * (PADE * 2) + (k0 + bK8) * 2;
                asm volatile("ldmatrix.sync.aligned.m8n8.x2.shared.b16 {%0,%1}, [%2];"
                             : "=r"(bb[0]), "=r"(bb[1]) : "r"(addr));
#pragma unroll
                for (int mi = 0; mi < 2; mi++) {
                    asm volatile(
                        "mma.sync.aligned.m16n8k16.row.col.f32.bf16.bf16.f32 "
                        "{%0,%1,%2,%3}, {%4,%5,%6,%7}, {%8,%9}, {%0,%1,%2,%3};"
                        : "+f"(d[mi][ni][0]), "+f"(d[mi][ni][1]),
                          "+f"(d[mi][ni][2]), "+f"(d[mi][ni][3])
                        : "r"(a[mi][0]), "r"(a[mi][1]), "r"(a[mi][2]), "r"(a[mi][3]),
                          "r"(bb[0]), "r"(bb[1]));
                }
            }
        }
    }
}

// ---------------------------------------------------------------------------
// Sweep 1: rowsums of exp(s). No beta writes.  [measured 122us, regs=128]
// ---------------------------------------------------------------------------
__global__ void __launch_bounds__(256, 2) attn_sum_kernel() {
    extern __shared__ __align__(16) char smem[];
    __shared__ float srow[128];

    char* sAhi = smem;
    char* sAlo = smem + TILE_BYTES;
    char* sBhi = smem + 2 * TILE_BYTES;
    char* sBlo = smem + 3 * TILE_BYTES;

    const int b    = blockIdx.z;
    const int row0 = blockIdx.y * 128;
    const int col0 = blockIdx.x * 128;
    const int tid  = threadIdx.x;
    const int wid  = tid >> 5;
    const int lane = tid & 31;

    load_tiles(sAhi, sAlo, sBhi, sBlo, b, row0, col0, tid);
    if (tid < 128) srow[tid] = 0.0f;
    __syncthreads();

    const int wm = wid & 3, wn = wid >> 2;
    float d[2][8][4];
#pragma unroll
    for (int mi = 0; mi < 2; mi++)
#pragma unroll
        for (int ni = 0; ni < 8; ni++)
#pragma unroll
            for (int q = 0; q < 4; q++) d[mi][ni][q] = 0.0f;

    gemm_tile(sAhi, sAlo, sBhi, sBlo,
              wm * 32 + (lane & 15), (lane >> 4) * 8,
              wn * 64 + (lane & 7), ((lane >> 3) & 1) * 8, d);

    const int gRow = lane >> 2;
#pragma unroll
    for (int mi = 0; mi < 2; mi++) {
        const int rl0 = wm * 32 + mi * 16 + gRow;
        float s0 = 0.0f, s1 = 0.0f;
#pragma unroll
        for (int ni = 0; ni < 8; ni++) {
            s0 += __expf(d[mi][ni][0]) + __expf(d[mi][ni][1]);
            s1 += __expf(d[mi][ni][2]) + __expf(d[mi][ni][3]);
        }
        s0 += __shfl_xor_sync(0xffffffffu, s0, 1);
        s0 += __shfl_xor_sync(0xffffffffu, s0, 2);
        s1 += __shfl_xor_sync(0xffffffffu, s1, 1);
        s1 += __shfl_xor_sync(0xffffffffu, s1, 2);
        if ((lane & 3) == 0) {
            atomicAdd(&srow[rl0], s0);
            atomicAdd(&srow[rl0 + 8], s1);
        }
    }
    __syncthreads();
    if (tid < 128) atomicAdd(&g_rowsum[(size_t)b * N_ + row0 + tid], srow[tid]);
}

// ---------------------------------------------------------------------------
// Sweep 2: recompute s, beta = exp(s) * rowinv, write once.
// Reciprocals preloaded to smem during tile-load phase -> epilogue reads LDS,
// keeping register count at/below attn_sum's (no spills).
// ---------------------------------------------------------------------------
__global__ void __launch_bounds__(256, 2) attn_write_kernel(float* __restrict__ beta) {
    extern __shared__ __align__(16) char smem[];
    __shared__ float sinv[128];

    char* sAhi = smem;
    char* sAlo = smem + TILE_BYTES;
    char* sBhi = smem + 2 * TILE_BYTES;
    char* sBlo = smem + 3 * TILE_BYTES;

    const int b    = blockIdx.z;
    const int row0 = blockIdx.y * 128;
    const int col0 = blockIdx.x * 128;
    const int tid  = threadIdx.x;
    const int wid  = tid >> 5;
    const int lane = tid & 31;

    load_tiles(sAhi, sAlo, sBhi, sBlo, b, row0, col0, tid);
    if (tid < 128) sinv[tid] = g_rowsum[(size_t)b * N_ + row0 + tid];  // reciprocals
    __syncthreads();

    const int wm = wid & 3, wn = wid >> 2;
    float d[2][8][4];
#pragma unroll
    for (int mi = 0; mi < 2; mi++)
#pragma unroll
        for (int ni = 0; ni < 8; ni++)
#pragma unroll
            for (int q = 0; q < 4; q++) d[mi][ni][q] = 0.0f;

    gemm_tile(sAhi, sAlo, sBhi, sBlo,
              wm * 32 + (lane & 15), (lane >> 4) * 8,
              wn * 64 + (lane & 7), ((lane >> 3) & 1) * 8, d);

    const int gRow = lane >> 2;
    const int cPair = (lane & 3) * 2;
#pragma unroll
    for (int mi = 0; mi < 2; mi++) {
        const int rl0 = wm * 32 + mi * 16 + gRow;
        const float inv0 = sinv[rl0];
        const float inv1 = sinv[rl0 + 8];
        const size_t r0 = (size_t)b * N_ + row0 + rl0;
        const size_t r1 = r0 + 8;
#pragma unroll
        for (int ni = 0; ni < 8; ni++) {
            const int col = col0 + wn * 64 + ni * 8 + cPair;
            *reinterpret_cast<float2*>(beta + r0 * (size_t)N_ + col) =
                make_float2(__expf(d[mi][ni][0]) * inv0, __expf(d[mi][ni][1]) * inv0);
            *reinterpret_cast<float2*>(beta + r1 * (size_t)N_ + col) =
                make_float2(__expf(d[mi][ni][2]) * inv1, __expf(d[mi][ni][3]) * inv1);
        }
    }
}

// ---------------------------------------------------------------------------
// Generic path (gamma != 0): h = x @ Wh.  Early-exits when gamma == 0.
// ---------------------------------------------------------------------------
__global__ void h_kernel(const float* __restrict__ x, const float* __restrict__ Wh,
                         const float* __restrict__ gamma) {
    if (gamma[0] == 0.0f) return;
    const int b = blockIdx.y;
    for (int nn = 0; nn < 16; nn++) {
        const int n = blockIdx.x * 16 + nn;
        const int c = threadIdx.x;
        const float* xr = x + ((size_t)b * N_ + n) * C_;
        float acc = 0.0f;
        for (int k = 0; k < C_; k++) acc = fmaf(xr[k], Wh[k * C_ + c], acc);
        g_h[((size_t)b * N_ + n) * C_ + c] = acc;
    }
}

// ---------------------------------------------------------------------------
// out = gamma * (beta @ h) + x  (pure vectorized copy when gamma == 0)
// ---------------------------------------------------------------------------
__global__ void __launch_bounds__(256) out_kernel(const float* __restrict__ x,
                                                  const float* __restrict__ gamma,
                                                  float* __restrict__ out,
                                                  const float* __restrict__ beta) {
    const float gm = gamma[0];
    const int i = blockIdx.x * 256 + threadIdx.x;      // float4 index
    if (gm == 0.0f) {
        reinterpret_cast<float4*>(out)[i] = reinterpret_cast<const float4*>(x)[i];
        return;
    }
    const int rowg = i >> 6;
    const int c0   = (i & 63) * 4;
    const float* brow = beta + (size_t)rowg * (size_t)N_;
    const int b = rowg >> 12;
    float acc[4] = {};
    for (int m = 0; m < N_; m++) {
        const float bv = brow[m];
        const float* hr = g_h + ((size_t)b * N_ + m) * C_ + c0;
#pragma unroll
        for (int q = 0; q < 4; q++) acc[q] = fmaf(bv, hr[q], acc[q]);
    }
    const size_t idx = (size_t)rowg * C_ + c0;
#pragma unroll
    for (int q = 0; q < 4; q++) out[idx + q] = fmaf(gm, acc[q], x[idx + q]);
}

// ---------------------------------------------------------------------------
extern "C" void kernel_launch(void* const* d_in, const int* in_sizes, int n_in,
                              void* d_out, int out_size) {
    const float* x     = (const float*)d_in[0];
    const float* Wf    = (const float*)d_in[1];
    const float* Wg    = (const float*)d_in[2];
    const float* Wh    = (const float*)d_in[3];
    const float* gamma = (const float*)d_in[4];

    float* out  = (float*)d_out;
    float* beta = out + (size_t)B_ * N_ * C_;

    cudaFuncSetAttribute(attn_sum_kernel, cudaFuncAttributeMaxDynamicSharedMemorySize,
                         4 * TILE_BYTES);
    cudaFuncSetAttribute(attn_write_kernel, cudaFuncAttributeMaxDynamicSharedMemorySize,
                         4 * TILE_BYTES);

    zero_rowsum_kernel<<<(B_ * N_) / 256, 256>>>();
    fg_kernel<<<dim3(N_ / 32, B_), 256>>>(x, Wf, Wg);
    h_kernel<<<dim3(N_ / 16, B_), 256>>>(x, Wh, gamma);
    attn_sum_kernel<<<dim3(N_ / 128, N_ / 128, B_), 256, 4 * TILE_BYTES>>>();
    inv_rowsum_kernel<<<(B_ * N_) / 256, 256>>>();
    attn_write_kernel<<<dim3(N_ / 128, N_ / 128, B_), 256, 4 * TILE_BYTES>>>(beta);
    out_kernel<<<(B_ * N_ * C_ / 4) / 256, 256>>>(x, gamma, out, beta);
}

// round 11
// speedup vs baseline: 1.3618x; 1.3618x over previous
#include <cuda_runtime.h>
#include <cuda_bf16.h>
#include <stdint.h>
#include <math.h>

#define B_ 4
#define N_ 4096
#define C_ 256
#define D_ 64

// ---- scratch (allocation-free contract) -----------------------------------
__device__ uint16_t g_ghi[B_ * N_ * D_];   // bf16 hi of g
__device__ uint16_t g_glo[B_ * N_ * D_];   // bf16 lo of g
__device__ uint16_t g_fhi[B_ * N_ * D_];   // bf16 hi of f
__device__ uint16_t g_flo[B_ * N_ * D_];   // bf16 lo of f
__device__ float    g_h[B_ * N_ * C_];     // only touched if gamma != 0

__device__ __forceinline__ uint32_t smem_u32(const void* p) {
    uint32_t a;
    asm("{ .reg .u64 t; cvta.to.shared.u64 t, %1; cvt.u32.u64 %0, t; }" : "=r"(a) : "l"(p));
    return a;
}
__device__ __forceinline__ void cp16(uint32_t dst, const void* src) {
    asm volatile("cp.async.cg.shared.global [%0], [%1], 16;" :: "r"(dst), "l"(src));
}
#define CP_COMMIT() asm volatile("cp.async.commit_group;" ::: "memory")
#define CP_WAIT0()  asm volatile("cp.async.wait_group 0;" ::: "memory")

#define LDSM4(r, addr) \
    asm volatile("ldmatrix.sync.aligned.m8n8.x4.shared.b16 {%0,%1,%2,%3}, [%4];" \
        : "=r"((r)[0]), "=r"((r)[1]), "=r"((r)[2]), "=r"((r)[3]) : "r"(addr))

#define MMA(dd, A, b0, b1) \
    asm volatile("mma.sync.aligned.m16n8k16.row.col.f32.bf16.bf16.f32 " \
        "{%0,%1,%2,%3}, {%4,%5,%6,%7}, {%8,%9}, {%0,%1,%2,%3};" \
        : "+f"((dd)[0]), "+f"((dd)[1]), "+f"((dd)[2]), "+f"((dd)[3]) \
        : "r"((A)[0]), "r"((A)[1]), "r"((A)[2]), "r"((A)[3]), "r"(b0), "r"(b1))

// smem geometry: 144B row stride (64 bf16 + 8 pad) -> conflict-free ldmatrix
#define ROWB      144
#define STRIP     32                          // rows per strip
#define NSTRIPS   (B_ * N_ / STRIP)           // 512
#define NCTAS     148
#define A_HALF    (STRIP * ROWB)              // 4608
#define A_BYTES   (A_HALF * 2)                // 9216
#define B_HALF    (128 * ROWB)                // 18432
#define B_BYTES   (B_HALF * 2)                // 36864
#define SB_OFF    A_BYTES
#define SMEM_BYTES (A_BYTES + 2 * B_BYTES)    // 82944

// fg kernel: 64 rows/block, x staged row-major with pad
#define XS_STRIDE 260
#define FG_SMEM   (64 * XS_STRIDE * 4)        // 66560

// ---------------------------------------------------------------------------
// f = x@Wf, g = x@Wg, emitted as bf16 hi/lo split.
// 2 rows per thread: each W LDS feeds 32 FMA (was 16) -> LSU traffic halved.
// ---------------------------------------------------------------------------
__global__ void __launch_bounds__(256) fg_kernel(const float* __restrict__ x,
                                                 const float* __restrict__ Wf,
                                                 const float* __restrict__ Wg) {
    extern __shared__ float xs[];              // [64][XS_STRIDE]
    __shared__ float ws[2][16][D_];

    const int b    = blockIdx.y;
    const int row0 = blockIdx.x * 64;
    const int r    = threadIdx.x >> 3;         // 0..31 (also handles r+32)
    const int dg   = threadIdx.x & 7;

    // load 64 rows x 256 cols of x, row-major (conflict-free)
    for (int i = threadIdx.x; i < 4096; i += 256) {
        int rr = i >> 6, c4 = i & 63;
        float4 v = reinterpret_cast<const float4*>(
            x + ((size_t)b * N_ + row0 + rr) * C_)[c4];
        float* dst = xs + rr * XS_STRIDE + c4 * 4;
        dst[0] = v.x; dst[1] = v.y; dst[2] = v.z; dst[3] = v.w;
    }

    float accf[2][8] = {}, accg[2][8] = {};
    for (int c0 = 0; c0 < C_; c0 += 16) {
        __syncthreads();
        {
            const float4* wf4 = reinterpret_cast<const float4*>(Wf + c0 * D_);
            const float4* wg4 = reinterpret_cast<const float4*>(Wg + c0 * D_);
            reinterpret_cast<float4*>(&ws[0][0][0])[threadIdx.x] = wf4[threadIdx.x];
            reinterpret_cast<float4*>(&ws[1][0][0])[threadIdx.x] = wg4[threadIdx.x];
        }
        __syncthreads();
#pragma unroll
        for (int cc = 0; cc < 16; cc++) {
            const float xv0 = xs[r * XS_STRIDE + c0 + cc];
            const float xv1 = xs[(r + 32) * XS_STRIDE + c0 + cc];
#pragma unroll
            for (int j = 0; j < 8; j++) {
                const float wfv = ws[0][cc][dg * 8 + j];
                const float wgv = ws[1][cc][dg * 8 + j];
                accf[0][j] = fmaf(xv0, wfv, accf[0][j]);
                accf[1][j] = fmaf(xv1, wfv, accf[1][j]);
                accg[0][j] = fmaf(xv0, wgv, accg[0][j]);
                accg[1][j] = fmaf(xv1, wgv, accg[1][j]);
            }
        }
    }

#pragma unroll
    for (int h = 0; h < 2; h++) {
        uint4 fh, fl, gh, gl;
        uint16_t* fhp = (uint16_t*)&fh; uint16_t* flp = (uint16_t*)&fl;
        uint16_t* ghp = (uint16_t*)&gh; uint16_t* glp = (uint16_t*)&gl;
#pragma unroll
        for (int j = 0; j < 8; j++) {
            __nv_bfloat16 h1 = __float2bfloat16_rn(accf[h][j]);
            __nv_bfloat16 l1 = __float2bfloat16_rn(accf[h][j] - __bfloat162float(h1));
            __nv_bfloat16 h2 = __float2bfloat16_rn(accg[h][j]);
            __nv_bfloat16 l2 = __float2bfloat16_rn(accg[h][j] - __bfloat162float(h2));
            fhp[j] = *(uint16_t*)&h1; flp[j] = *(uint16_t*)&l1;
            ghp[j] = *(uint16_t*)&h2; glp[j] = *(uint16_t*)&l2;
        }
        size_t off = ((size_t)b * N_ + row0 + r + h * 32) * D_ + dg * 8;
        *reinterpret_cast<uint4*>(g_fhi + off) = fh;
        *reinterpret_cast<uint4*>(g_flo + off) = fl;
        *reinterpret_cast<uint4*>(g_ghi + off) = gh;
        *reinterpret_cast<uint4*>(g_glo + off) = gl;
    }
}

// ---------------------------------------------------------------------------
// Persistent single-sweep attention with in-L2 renormalization.
// 148 CTAs; each CTA owns 32-row strips (strip = 512KB of beta, stays in L2
// between the unnormalized-exp write and the normalize re-read).
// [measured: best config, ~345us]
// ---------------------------------------------------------------------------
__device__ __forceinline__ void load_a_strip(uint32_t sb, int strip, int tid) {
    const int b    = strip >> 7;
    const int row0 = (strip & 127) * STRIP;
    for (int i = tid; i < 512; i += 256) {
        int half = i >> 8, j = i & 255, r = j >> 3, c = j & 7;
        const uint16_t* src = (half ? g_glo : g_ghi) + ((size_t)b * N_ + row0 + r) * D_ + c * 8;
        cp16(sb + half * A_HALF + r * ROWB + c * 16, src);
    }
}

__device__ __forceinline__ void load_b_tile(uint32_t dst, int b, int col0, int tid) {
#pragma unroll 2
    for (int i = tid; i < 2048; i += 256) {
        int half = i >> 10, j = i & 1023, r = j >> 3, c = j & 7;
        const uint16_t* src = (half ? g_flo : g_fhi) + ((size_t)b * N_ + col0 + r) * D_ + c * 8;
        cp16(dst + half * B_HALF + r * ROWB + c * 16, src);
    }
}

__global__ void __launch_bounds__(256, 1) attn_persist_kernel(float* __restrict__ beta) {
    extern __shared__ __align__(16) char smem[];
    __shared__ float srow[STRIP];
    __shared__ float sinv[STRIP];

    const uint32_t sb = smem_u32(smem);
    const int tid  = threadIdx.x;
    const int wid  = tid >> 5;
    const int lane = tid & 31;
    const int wn   = wid;

    const uint32_t aRow = lane & 15;
    const uint32_t aK8  = (lane >> 4) * 8;
    const uint32_t bRow = wn * 16 + ((lane >> 3) & 1) * 8 + (lane & 7);
    const uint32_t bK8  = (lane >> 4) * 8;
    const int gRow  = lane >> 2;
    const int cPair = (lane & 3) * 2;

    if (tid < STRIP) srow[tid] = 0.0f;

    {
        int s0 = blockIdx.x;
        if (s0 < NSTRIPS) {
            load_a_strip(sb, s0, tid);
            load_b_tile(sb + SB_OFF, s0 >> 7, 0, tid);
            CP_COMMIT();
        }
    }

    for (int strip = blockIdx.x; strip < NSTRIPS; strip += NCTAS) {
        const int b    = strip >> 7;
        const int row0 = (strip & 127) * STRIP;

        CP_WAIT0();
        __syncthreads();

        float rsum[4] = {0.0f, 0.0f, 0.0f, 0.0f};

        for (int t = 0; t < 32; t++) {
            const uint32_t sB = sb + SB_OFF + (t & 1) * B_BYTES;
            if (t < 31) {
                load_b_tile(sb + SB_OFF + ((t + 1) & 1) * B_BYTES, b, (t + 1) * 128, tid);
                CP_COMMIT();
            }

            float d[2][2][4] = {};
#pragma unroll
            for (int term = 0; term < 3; term++) {
                const uint32_t Ab = sb + (term == 2 ? A_HALF : 0);
                const uint32_t Bb = sB + (term == 1 ? B_HALF : 0);
#pragma unroll
                for (int k0 = 0; k0 < 64; k0 += 16) {
                    uint32_t a[2][4];
#pragma unroll
                    for (int mi = 0; mi < 2; mi++)
                        LDSM4(a[mi], Ab + (aRow + mi * 16) * ROWB + (k0 + aK8) * 2);
                    uint32_t bb[4];
                    LDSM4(bb, Bb + bRow * ROWB + (k0 + bK8) * 2);
#pragma unroll
                    for (int mi = 0; mi < 2; mi++) {
                        MMA(d[mi][0], a[mi], bb[0], bb[2]);
                        MMA(d[mi][1], a[mi], bb[1], bb[3]);
                    }
                }
            }

            const int col0 = t * 128;
#pragma unroll
            for (int mi = 0; mi < 2; mi++) {
                const int rl0 = mi * 16 + gRow;
                const size_t r0 = (size_t)b * N_ + row0 + rl0;
                const size_t r1 = r0 + 8;
                float s0 = 0.0f, s1 = 0.0f;
#pragma unroll
                for (int ni = 0; ni < 2; ni++) {
                    float e0 = __expf(d[mi][ni][0]);
                    float e1 = __expf(d[mi][ni][1]);
                    float e2 = __expf(d[mi][ni][2]);
                    float e3 = __expf(d[mi][ni][3]);
                    const int col = col0 + wn * 16 + ni * 8 + cPair;
                    *reinterpret_cast<float2*>(beta + r0 * (size_t)N_ + col) = make_float2(e0, e1);
                    *reinterpret_cast<float2*>(beta + r1 * (size_t)N_ + col) = make_float2(e2, e3);
                    s0 += e0 + e1;
                    s1 += e2 + e3;
                }
                rsum[mi * 2]     += s0;
                rsum[mi * 2 + 1] += s1;
            }
            CP_WAIT0();
            __syncthreads();
        }

#pragma unroll
        for (int mi = 0; mi < 2; mi++) {
            float s0 = rsum[mi * 2], s1 = rsum[mi * 2 + 1];
            s0 += __shfl_xor_sync(0xffffffffu, s0, 1);
            s0 += __shfl_xor_sync(0xffffffffu, s0, 2);
            s1 += __shfl_xor_sync(0xffffffffu, s1, 1);
            s1 += __shfl_xor_sync(0xffffffffu, s1, 2);
            if ((lane & 3) == 0) {
                atomicAdd(&srow[mi * 16 + gRow], s0);
                atomicAdd(&srow[mi * 16 + gRow + 8], s1);
            }
        }
        __syncthreads();
        if (tid < STRIP) sinv[tid] = 1.0f / srow[tid];
        __syncthreads();
        if (tid < STRIP) srow[tid] = 0.0f;

        const int nxt = strip + NCTAS;
        if (nxt < NSTRIPS) {
            load_a_strip(sb, nxt, tid);
            load_b_tile(sb + SB_OFF, nxt >> 7, 0, tid);
            CP_COMMIT();
        }

        {
            const int r  = tid >> 3;
            const int c8 = tid & 7;
            const float inv = sinv[r];
            float4* p = reinterpret_cast<float4*>(beta + ((size_t)b * N_ + row0 + r) * N_) + c8;
#pragma unroll 1
            for (int j = 0; j < 128; j += 8) {
                float4 v[8];
#pragma unroll
                for (int u = 0; u < 8; u++) v[u] = __ldcs(p + (size_t)(j + u) * 8);
#pragma unroll
                for (int u = 0; u < 8; u++) {
                    v[u].x *= inv; v[u].y *= inv; v[u].z *= inv; v[u].w *= inv;
                }
#pragma unroll
                for (int u = 0; u < 8; u++) __stcs(p + (size_t)(j + u) * 8, v[u]);
            }
        }
    }
}

// ---------------------------------------------------------------------------
// Generic path (gamma != 0): h = x @ Wh.  Early-exits when gamma == 0.
// ---------------------------------------------------------------------------
__global__ void h_kernel(const float* __restrict__ x, const float* __restrict__ Wh,
                         const float* __restrict__ gamma) {
    if (gamma[0] == 0.0f) return;
    const int b = blockIdx.y;
    for (int nn = 0; nn < 16; nn++) {
        const int n = blockIdx.x * 16 + nn;
        const int c = threadIdx.x;
        const float* xr = x + ((size_t)b * N_ + n) * C_;
        float acc = 0.0f;
        for (int k = 0; k < C_; k++) acc = fmaf(xr[k], Wh[k * C_ + c], acc);
        g_h[((size_t)b * N_ + n) * C_ + c] = acc;
    }
}

// ---------------------------------------------------------------------------
// out = gamma * (beta @ h) + x  (pure vectorized copy when gamma == 0)
// ---------------------------------------------------------------------------
__global__ void __launch_bounds__(256) out_kernel(const float* __restrict__ x,
                                                  const float* __restrict__ gamma,
                                                  float* __restrict__ out,
                                                  const float* __restrict__ beta) {
    const float gm = gamma[0];
    const int i = blockIdx.x * 256 + threadIdx.x;
    if (gm == 0.0f) {
        reinterpret_cast<float4*>(out)[i] = reinterpret_cast<const float4*>(x)[i];
        return;
    }
    const int rowg = i >> 6;
    const int c0   = (i & 63) * 4;
    const float* brow = beta + (size_t)rowg * (size_t)N_;
    const int b = rowg >> 12;
    float acc[4] = {};
    for (int m = 0; m < N_; m++) {
        const float bv = brow[m];
        const float* hr = g_h + ((size_t)b * N_ + m) * C_ + c0;
#pragma unroll
        for (int q = 0; q < 4; q++) acc[q] = fmaf(bv, hr[q], acc[q]);
    }
    const size_t idx = (size_t)rowg * C_ + c0;
#pragma unroll
    for (int q = 0; q < 4; q++) out[idx + q] = fmaf(gm, acc[q], x[idx + q]);
}

// ---------------------------------------------------------------------------
extern "C" void kernel_launch(void* const* d_in, const int* in_sizes, int n_in,
                              void* d_out, int out_size) {
    const float* x     = (const float*)d_in[0];
    const float* Wf    = (const float*)d_in[1];
    const float* Wg    = (const float*)d_in[2];
    const float* Wh    = (const float*)d_in[3];
    const float* gamma = (const float*)d_in[4];

    float* out  = (float*)d_out;
    float* beta = out + (size_t)B_ * N_ * C_;

    cudaFuncSetAttribute(attn_persist_kernel, cudaFuncAttributeMaxDynamicSharedMemorySize,
                         SMEM_BYTES);
    cudaFuncSetAttribute(fg_kernel, cudaFuncAttributeMaxDynamicSharedMemorySize,
                         FG_SMEM);

    fg_kernel<<<dim3(N_ / 64, B_), 256, FG_SMEM>>>(x, Wf, Wg);
    h_kernel<<<dim3(N_ / 16, B_), 256>>>(x, Wh, gamma);
    attn_persist_kernel<<<NCTAS, 256, SMEM_BYTES>>>(beta);
    out_kernel<<<(B_ * N_ * C_ / 4) / 256, 256>>>(x, gamma, out, beta);
}

// round 13
// speedup vs baseline: 1.4259x; 1.0470x over previous
#include <cuda_runtime.h>
#include <cuda_bf16.h>
#include <stdint.h>
#include <math.h>

#define B_ 4
#define N_ 4096
#define C_ 256
#define D_ 64

// ---- scratch (allocation-free contract) -----------------------------------
__device__ uint16_t g_ghi[B_ * N_ * D_];   // bf16 hi of g
__device__ uint16_t g_glo[B_ * N_ * D_];   // bf16 lo of g
__device__ uint16_t g_fhi[B_ * N_ * D_];   // bf16 hi of f
__device__ uint16_t g_flo[B_ * N_ * D_];   // bf16 lo of f
__device__ float    g_h[B_ * N_ * C_];     // only touched if gamma != 0

__device__ __forceinline__ uint32_t smem_u32(const void* p) {
    uint32_t a;
    asm("{ .reg .u64 t; cvta.to.shared.u64 t, %1; cvt.u32.u64 %0, t; }" : "=r"(a) : "l"(p));
    return a;
}
__device__ __forceinline__ void cp16(uint32_t dst, const void* src) {
    asm volatile("cp.async.cg.shared.global [%0], [%1], 16;" :: "r"(dst), "l"(src));
}
#define CP_COMMIT() asm volatile("cp.async.commit_group;" ::: "memory")
#define CP_WAIT0()  asm volatile("cp.async.wait_group 0;" ::: "memory")
#define CP_WAIT1()  asm volatile("cp.async.wait_group 1;" ::: "memory")
#define BAR_WG(id)  asm volatile("bar.sync %0, 128;" :: "r"(id) : "memory")

#define LDSM4(r, addr) \
    asm volatile("ldmatrix.sync.aligned.m8n8.x4.shared.b16 {%0,%1,%2,%3}, [%4];" \
        : "=r"((r)[0]), "=r"((r)[1]), "=r"((r)[2]), "=r"((r)[3]) : "r"(addr))

#define MMA(dd, A, b0, b1) \
    asm volatile("mma.sync.aligned.m16n8k16.row.col.f32.bf16.bf16.f32 " \
        "{%0,%1,%2,%3}, {%4,%5,%6,%7}, {%8,%9}, {%0,%1,%2,%3};" \
        : "+f"((dd)[0]), "+f"((dd)[1]), "+f"((dd)[2]), "+f"((dd)[3]) \
        : "r"((A)[0]), "r"((A)[1]), "r"((A)[2]), "r"((A)[3]), "r"(b0), "r"(b1))

// smem geometry: 144B row stride (64 bf16 + 8 pad) -> conflict-free ldmatrix
#define ROWB      144
#define STRIP     32
#define NSTRIPS   (B_ * N_ / STRIP)           // 512
#define NCTAS     148
#define A_HALF    (STRIP * ROWB)              // 4608
#define A_BYTES   (A_HALF * 2)                // 9216 (per warpgroup copy)
#define B_HALF    (128 * ROWB)                // 18432
#define B_BYTES   (B_HALF * 2)                // 36864
#define SB_OFF    (2 * A_BYTES)               // B buffers after both A copies
#define SMEM_BYTES (2 * A_BYTES + 4 * B_BYTES) // 165888

// fg kernel: 64 rows/block, x staged row-major with pad
#define XS_STRIDE 260
#define FG_SMEM   (64 * XS_STRIDE * 4)        // 66560

// ---------------------------------------------------------------------------
// f = x@Wf, g = x@Wg, emitted as bf16 hi/lo split.  [measured ~10us]
// ---------------------------------------------------------------------------
__global__ void __launch_bounds__(256) fg_kernel(const float* __restrict__ x,
                                                 const float* __restrict__ Wf,
                                                 const float* __restrict__ Wg) {
    extern __shared__ float xs[];              // [64][XS_STRIDE]
    __shared__ float ws[2][16][D_];

    const int b    = blockIdx.y;
    const int row0 = blockIdx.x * 64;
    const int r    = threadIdx.x >> 3;
    const int dg   = threadIdx.x & 7;

    for (int i = threadIdx.x; i < 4096; i += 256) {
        int rr = i >> 6, c4 = i & 63;
        float4 v = reinterpret_cast<const float4*>(
            x + ((size_t)b * N_ + row0 + rr) * C_)[c4];
        float* dst = xs + rr * XS_STRIDE + c4 * 4;
        dst[0] = v.x; dst[1] = v.y; dst[2] = v.z; dst[3] = v.w;
    }

    float accf[2][8] = {}, accg[2][8] = {};
    for (int c0 = 0; c0 < C_; c0 += 16) {
        __syncthreads();
        {
            const float4* wf4 = reinterpret_cast<const float4*>(Wf + c0 * D_);
            const float4* wg4 = reinterpret_cast<const float4*>(Wg + c0 * D_);
            reinterpret_cast<float4*>(&ws[0][0][0])[threadIdx.x] = wf4[threadIdx.x];
            reinterpret_cast<float4*>(&ws[1][0][0])[threadIdx.x] = wg4[threadIdx.x];
        }
        __syncthreads();
#pragma unroll
        for (int cc = 0; cc < 16; cc++) {
            const float xv0 = xs[r * XS_STRIDE + c0 + cc];
            const float xv1 = xs[(r + 32) * XS_STRIDE + c0 + cc];
#pragma unroll
            for (int j = 0; j < 8; j++) {
                const float wfv = ws[0][cc][dg * 8 + j];
                const float wgv = ws[1][cc][dg * 8 + j];
                accf[0][j] = fmaf(xv0, wfv, accf[0][j]);
                accf[1][j] = fmaf(xv1, wfv, accf[1][j]);
                accg[0][j] = fmaf(xv0, wgv, accg[0][j]);
                accg[1][j] = fmaf(xv1, wgv, accg[1][j]);
            }
        }
    }

#pragma unroll
    for (int h = 0; h < 2; h++) {
        uint4 fh, fl, gh, gl;
        uint16_t* fhp = (uint16_t*)&fh; uint16_t* flp = (uint16_t*)&fl;
        uint16_t* ghp = (uint16_t*)&gh; uint16_t* glp = (uint16_t*)&gl;
#pragma unroll
        for (int j = 0; j < 8; j++) {
            __nv_bfloat16 h1 = __float2bfloat16_rn(accf[h][j]);
            __nv_bfloat16 l1 = __float2bfloat16_rn(accf[h][j] - __bfloat162float(h1));
            __nv_bfloat16 h2 = __float2bfloat16_rn(accg[h][j]);
            __nv_bfloat16 l2 = __float2bfloat16_rn(accg[h][j] - __bfloat162float(h2));
            fhp[j] = *(uint16_t*)&h1; flp[j] = *(uint16_t*)&l1;
            ghp[j] = *(uint16_t*)&h2; glp[j] = *(uint16_t*)&l2;
        }
        size_t off = ((size_t)b * N_ + row0 + r + h * 32) * D_ + dg * 8;
        *reinterpret_cast<uint4*>(g_fhi + off) = fh;
        *reinterpret_cast<uint4*>(g_flo + off) = fl;
        *reinterpret_cast<uint4*>(g_ghi + off) = gh;
        *reinterpret_cast<uint4*>(g_glo + off) = gl;
    }
}

// ---------------------------------------------------------------------------
// Persistent attention, two independent warpgroup pipelines per CTA.
// wg0 handles column tiles 0..15, wg1 tiles 16..31, each with private A copy
// and double-buffered B; named barriers keep pipelines decoupled so one wg's
// epilogue overlaps the other's MMAs. In-L2 renorm as before.
// ---------------------------------------------------------------------------
__device__ __forceinline__ void load_a_wg(uint32_t dstA, int strip, int wtid) {
    const int b    = strip >> 7;
    const int row0 = (strip & 127) * STRIP;
    for (int i = wtid; i < 512; i += 128) {
        int half = i >> 8, j = i & 255, r = j >> 3, c = j & 7;
        const uint16_t* src = (half ? g_glo : g_ghi) + ((size_t)b * N_ + row0 + r) * D_ + c * 8;
        cp16(dstA + half * A_HALF + r * ROWB + c * 16, src);
    }
}

__device__ __forceinline__ void load_b_wg(uint32_t dst, int b, int col0, int wtid) {
#pragma unroll 2
    for (int i = wtid; i < 2048; i += 128) {
        int half = i >> 10, j = i & 1023, r = j >> 3, c = j & 7;
        const uint16_t* src = (half ? g_flo : g_fhi) + ((size_t)b * N_ + col0 + r) * D_ + c * 8;
        cp16(dst + half * B_HALF + r * ROWB + c * 16, src);
    }
}

__global__ void __launch_bounds__(256, 1) attn_persist_kernel(float* __restrict__ beta) {
    extern __shared__ __align__(16) char smem[];
    __shared__ float srow[STRIP];
    __shared__ float sinv[STRIP];

    const uint32_t sb = smem_u32(smem);
    const int tid  = threadIdx.x;
    const int wg   = tid >> 7;                 // warpgroup 0/1
    const int wtid = tid & 127;
    const int w    = (tid >> 5) & 3;           // warp in wg
    const int lane = tid & 31;

    const uint32_t sA   = sb + wg * A_BYTES;
    const uint32_t sB0  = sb + SB_OFF + (wg * 2) * B_BYTES;

    const uint32_t aRow = lane & 15;
    const uint32_t aK8  = (lane >> 4) * 8;
    const uint32_t bRow = w * 32 + ((lane >> 3) & 1) * 8 + (lane & 7);
    const uint32_t bK8  = (lane >> 4) * 8;
    const int gRow  = lane >> 2;
    const int cPair = (lane & 3) * 2;
    const int barid = 1 + wg;

    if (tid < STRIP) srow[tid] = 0.0f;
    __syncthreads();

    // prologue: own-wg A + first B tile of own half
    {
        int s0 = blockIdx.x;
        load_a_wg(sA, s0, wtid);
        load_b_wg(sB0, s0 >> 7, wg * 16 * 128, wtid);
        CP_COMMIT();
    }

    for (int strip = blockIdx.x; strip < NSTRIPS; strip += NCTAS) {
        const int b    = strip >> 7;
        const int row0 = (strip & 127) * STRIP;

        float rsum[4] = {0.0f, 0.0f, 0.0f, 0.0f};

        for (int t = 0; t < 16; t++) {
            const uint32_t sBcur = sB0 + (t & 1) * B_BYTES;
            BAR_WG(barid);                         // all wg warps done reading other buffer
            if (t < 15) {
                load_b_wg(sB0 + ((t + 1) & 1) * B_BYTES, b, (wg * 16 + t + 1) * 128, wtid);
                CP_COMMIT();
                CP_WAIT1();                        // current tile's data arrived
            } else {
                CP_WAIT0();
            }
            BAR_WG(barid);                         // visibility of current buffer

            float d[2][4][4] = {};
#pragma unroll
            for (int term = 0; term < 3; term++) {
                const uint32_t Ab = sA + (term == 2 ? A_HALF : 0);
                const uint32_t Bb = sBcur + (term == 1 ? B_HALF : 0);
#pragma unroll
                for (int k0 = 0; k0 < 64; k0 += 16) {
                    uint32_t a[2][4];
                    LDSM4(a[0], Ab + aRow * ROWB + (k0 + aK8) * 2);
                    LDSM4(a[1], Ab + (aRow + 16) * ROWB + (k0 + aK8) * 2);
                    uint32_t b0[4], b1[4];
                    LDSM4(b0, Bb + bRow * ROWB + (k0 + bK8) * 2);
                    LDSM4(b1, Bb + (bRow + 16) * ROWB + (k0 + bK8) * 2);
#pragma unroll
                    for (int mi = 0; mi < 2; mi++) {
                        MMA(d[mi][0], a[mi], b0[0], b0[2]);
                        MMA(d[mi][1], a[mi], b0[1], b0[3]);
                        MMA(d[mi][2], a[mi], b1[0], b1[2]);
                        MMA(d[mi][3], a[mi], b1[1], b1[3]);
                    }
                }
            }

            const int colbase = (wg * 16 + t) * 128 + w * 32;
#pragma unroll
            for (int mi = 0; mi < 2; mi++) {
                const int rl0 = mi * 16 + gRow;
                const size_t r0 = (size_t)b * N_ + row0 + rl0;
                const size_t r1 = r0 + 8;
                float s0 = 0.0f, s1 = 0.0f;
#pragma unroll
                for (int ni = 0; ni < 4; ni++) {
                    float e0 = __expf(d[mi][ni][0]);
                    float e1 = __expf(d[mi][ni][1]);
                    float e2 = __expf(d[mi][ni][2]);
                    float e3 = __expf(d[mi][ni][3]);
                    const int col = colbase + ni * 8 + cPair;
                    *reinterpret_cast<float2*>(beta + r0 * (size_t)N_ + col) = make_float2(e0, e1);
                    *reinterpret_cast<float2*>(beta + r1 * (size_t)N_ + col) = make_float2(e2, e3);
                    s0 += e0 + e1;
                    s1 += e2 + e3;
                }
                rsum[mi * 2]     += s0;
                rsum[mi * 2 + 1] += s1;
            }
        }

        // ---- combine rowsums across both warpgroups ----
#pragma unroll
        for (int mi = 0; mi < 2; mi++) {
            float s0 = rsum[mi * 2], s1 = rsum[mi * 2 + 1];
            s0 += __shfl_xor_sync(0xffffffffu, s0, 1);
            s0 += __shfl_xor_sync(0xffffffffu, s0, 2);
            s1 += __shfl_xor_sync(0xffffffffu, s1, 1);
            s1 += __shfl_xor_sync(0xffffffffu, s1, 2);
            if ((lane & 3) == 0) {
                atomicAdd(&srow[mi * 16 + gRow], s0);
                atomicAdd(&srow[mi * 16 + gRow + 8], s1);
            }
        }
        __syncthreads();
        if (tid < STRIP) sinv[tid] = 1.0f / srow[tid];
        __syncthreads();
        if (tid < STRIP) srow[tid] = 0.0f;

        // ---- prefetch next strip (own wg) before norm ----
        const int nxt = strip + NCTAS;
        if (nxt < NSTRIPS) {
            load_a_wg(sA, nxt, wtid);
            load_b_wg(sB0, nxt >> 7, wg * 16 * 128, wtid);
            CP_COMMIT();
        }

        // ---- normalize own strip from L2 (evict-first both directions) ----
        {
            const int r  = tid >> 3;
            const int c8 = tid & 7;
            const float inv = sinv[r];
            float4* p = reinterpret_cast<float4*>(beta + ((size_t)b * N_ + row0 + r) * N_) + c8;
#pragma unroll 1
            for (int j = 0; j < 128; j += 8) {
                float4 v[8];
#pragma unroll
                for (int u = 0; u < 8; u++) v[u] = __ldcs(p + (size_t)(j + u) * 8);
#pragma unroll
                for (int u = 0; u < 8; u++) {
                    v[u].x *= inv; v[u].y *= inv; v[u].z *= inv; v[u].w *= inv;
                }
#pragma unroll
                for (int u = 0; u < 8; u++) __stcs(p + (size_t)(j + u) * 8, v[u]);
            }
        }
        __syncthreads();   // norm done before srow reuse / next strip barriers
    }
}

// ---------------------------------------------------------------------------
// Generic path (gamma != 0): h = x @ Wh.  Early-exits when gamma == 0.
// ---------------------------------------------------------------------------
__global__ void h_kernel(const float* __restrict__ x, const float* __restrict__ Wh,
                         const float* __restrict__ gamma) {
    if (gamma[0] == 0.0f) return;
    const int b = blockIdx.y;
    for (int nn = 0; nn < 16; nn++) {
        const int n = blockIdx.x * 16 + nn;
        const int c = threadIdx.x;
        const float* xr = x + ((size_t)b * N_ + n) * C_;
        float acc = 0.0f;
        for (int k = 0; k < C_; k++) acc = fmaf(xr[k], Wh[k * C_ + c], acc);
        g_h[((size_t)b * N_ + n) * C_ + c] = acc;
    }
}

// ---------------------------------------------------------------------------
// out = gamma * (beta @ h) + x  (pure vectorized copy when gamma == 0)
// ---------------------------------------------------------------------------
__global__ void __launch_bounds__(256) out_kernel(const float* __restrict__ x,
                                                  const float* __restrict__ gamma,
                                                  float* __restrict__ out,
                                                  const float* __restrict__ beta) {
    const float gm = gamma[0];
    const int i = blockIdx.x * 256 + threadIdx.x;
    if (gm == 0.0f) {
        reinterpret_cast<float4*>(out)[i] = reinterpret_cast<const float4*>(x)[i];
        return;
    }
    const int rowg = i >> 6;
    const int c0   = (i & 63) * 4;
    const float* brow = beta + (size_t)rowg * (size_t)N_;
    const int b = rowg >> 12;
    float acc[4] = {};
    for (int m = 0; m < N_; m++) {
        const float bv = brow[m];
        const float* hr = g_h + ((size_t)b * N_ + m) * C_ + c0;
#pragma unroll
        for (int q = 0; q < 4; q++) acc[q] = fmaf(bv, hr[q], acc[q]);
    }
    const size_t idx = (size_t)rowg * C_ + c0;
#pragma unroll
    for (int q = 0; q < 4; q++) out[idx + q] = fmaf(gm, acc[q], x[idx + q]);
}

// ---------------------------------------------------------------------------
extern "C" void kernel_launch(void* const* d_in, const int* in_sizes, int n_in,
                              void* d_out, int out_size) {
    const float* x     = (const float*)d_in[0];
    const float* Wf    = (const float*)d_in[1];
    const float* Wg    = (const float*)d_in[2];
    const float* Wh    = (const float*)d_in[3];
    const float* gamma = (const float*)d_in[4];

    float* out  = (float*)d_out;
    float* beta = out + (size_t)B_ * N_ * C_;

    cudaFuncSetAttribute(attn_persist_kernel, cudaFuncAttributeMaxDynamicSharedMemorySize,
                         SMEM_BYTES);
    cudaFuncSetAttribute(fg_kernel, cudaFuncAttributeMaxDynamicSharedMemorySize,
                         FG_SMEM);

    fg_kernel<<<dim3(N_ / 64, B_), 256, FG_SMEM>>>(x, Wf, Wg);
    h_kernel<<<dim3(N_ / 16, B_), 256>>>(x, Wh, gamma);
    attn_persist_kernel<<<NCTAS, 256, SMEM_BYTES>>>(beta);
    out_kernel<<<(B_ * N_ * C_ / 4) / 256, 256>>>(x, gamma, out, beta);
}